// round 13
// baseline (speedup 1.0000x reference)
#include <cuda_runtime.h>
#include <cuda_fp16.h>
#include <math.h>
#include <stdint.h>

#define B_TOT 8192

// ecc: NC=7 chunks of K=64; A tile/chunk image 8KB, tile total 57344 B.
// err: NC=5; tile total 40960 B. B images: 32KB per chunk.
#define A_TILE_ECC 57344
#define A_TILE_ERR 40960

// ============================================================================
// Device globals (A and B stored as PRE-SWIZZLED chunk-major smem images)
// ============================================================================
__device__ __align__(16) __half g_B_ecc[7 * 16384];    // 7 chunks x 32KB
__device__ __align__(16) __half g_B_err[5 * 16384];
__device__ __align__(16) __half g_A_ecc[B_TOT * 448];  // [tile][chunk][img]
__device__ __align__(16) __half g_A_err[B_TOT * 320];
__device__ __align__(16) __half g_WeT[64 * 64];        // We^T fp16 [n][k]
__device__ __align__(16) __half g_Ah_ehr[B_TOT * 64];
__device__ float g_bias_part[28 * 256];

// ---------------------------------------------------------------------------
#define MMA16816(d, a, b0_, b1_) \
    asm volatile( \
        "mma.sync.aligned.m16n8k16.row.col.f32.f16.f16.f32 " \
        "{%0,%1,%2,%3}, {%4,%5,%6,%7}, {%8,%9}, {%0,%1,%2,%3};" \
        : "+f"((d)[0]), "+f"((d)[1]), "+f"((d)[2]), "+f"((d)[3]) \
        : "r"((a)[0]), "r"((a)[1]), "r"((a)[2]), "r"((a)[3]), \
          "r"(b0_), "r"(b1_))

#define LDSM_X4(r0, r1, r2, r3, addr) \
    asm volatile( \
        "ldmatrix.sync.aligned.m8n8.x4.shared.b16 {%0,%1,%2,%3}, [%4];" \
        : "=r"(r0), "=r"(r1), "=r"(r2), "=r"(r3) : "r"(addr))

#define CP_ASYNC16(dst, src) \
    asm volatile("cp.async.cg.shared.global [%0], [%1], 16;" \
        :: "r"(dst), "l"(src) : "memory")
#define CP_COMMIT() asm volatile("cp.async.commit_group;" ::: "memory")
#define CP_WAIT0()  asm volatile("cp.async.wait_group 0;" ::: "memory")

#define CP_BULK(dst, src, bytes, mbar) \
    asm volatile( \
        "cp.async.bulk.shared::cta.global.mbarrier::complete_tx::bytes " \
        "[%0], [%1], %2, [%3];" \
        :: "r"(dst), "l"(src), "r"(bytes), "r"(mbar) : "memory")

#define MBARRIER_INIT(mbar, count) \
    asm volatile("mbarrier.init.shared.b64 [%0], %1;" \
        :: "r"((uint32_t)(mbar)), "r"((uint32_t)(count)) : "memory")
#define MBARRIER_EXPECT_TX(mbar, bytes) \
    asm volatile("mbarrier.arrive.expect_tx.shared.b64 _, [%0], %1;" \
        :: "r"((uint32_t)(mbar)), "r"((uint32_t)(bytes)) : "memory")
#define MBARRIER_WAIT_PARITY(mbar_addr, phase_parity) do { \
    uint32_t _mbar = (uint32_t)(mbar_addr); \
    uint32_t _parity = (uint32_t)(phase_parity); \
    uint32_t _done; \
    asm volatile( \
        "{\n\t.reg .pred p;\n\t" \
        "mbarrier.try_wait.parity.acquire.cta.shared::cta.b64 p, [%1], %2;\n\t" \
        "selp.b32 %0, 1, 0, p;\n\t}" \
        : "=r"(_done) : "r"(_mbar), "r"(_parity) : "memory"); \
    if (!_done) { \
        asm volatile( \
            "{\n\t.reg .pred P1;\n\t" \
            "WAIT_LOOP_%=:\n\t" \
            "mbarrier.try_wait.parity.acquire.cta.shared::cta.b64 P1, [%0], %1, 0x989680;\n\t" \
            "@P1 bra.uni WAIT_DONE_%=;\n\t" \
            "bra.uni WAIT_LOOP_%=;\n\t" \
            "WAIT_DONE_%=:\n\t}" \
            :: "r"(_mbar), "r"(_parity) : "memory"); \
    } \
} while(0)

#define SWZ(off) ((off) ^ (((off) >> 3) & 0x70))

__device__ __forceinline__ uint32_t smem_to_u32(const void* p) {
    uint32_t a;
    asm("{ .reg .u64 t; cvta.to.shared.u64 t, %1; cvt.u32.u64 %0, t; }"
        : "=r"(a) : "l"(p));
    return a;
}
__device__ __forceinline__ uint32_t pack_hi16(float a, float b) {
    return (uint32_t)__half_as_ushort(__float2half(a)) |
           ((uint32_t)__half_as_ushort(__float2half(b)) << 16);
}
__device__ __forceinline__ float tanh_fast(float x) {
    float y;
    asm("tanh.approx.f32 %0, %1;" : "=f"(y) : "f"(x));
    return y;
}

// ============================================================================
// K1: merged precompute + fp16 conversions (chunk-major pre-swizzled images).
//  0..139   : R rows (Weff inline) -> g_B_* images
//  140..167 : c0 + bias_part       168: We^T + ehr handled below
//  169..424 : ecc -> images (32 rows/blk)   425..680: err (32 rows/blk)
//  681..744 : ehr -> fp16 (128 rows/blk)
// ============================================================================
__global__ __launch_bounds__(256) void precompute(
    const float* __restrict__ ecc, const float* __restrict__ err,
    const float* __restrict__ ehr,
    const float* __restrict__ wt_ecc, const float* __restrict__ bt_ecc,
    const float* __restrict__ wt_err, const float* __restrict__ bt_err,
    const float* __restrict__ W0_ecc, const float* __restrict__ W1_ecc,
    const float* __restrict__ b_ecc,
    const float* __restrict__ W0_err, const float* __restrict__ W1_err,
    const float* __restrict__ b_err,
    const float* __restrict__ Wp_ecc, const float* __restrict__ bp_ecc,
    const float* __restrict__ Wp_err, const float* __restrict__ bp_err,
    const float* __restrict__ We)
{
    const int blk = blockIdx.x;
    const int t   = threadIdx.x;

    if (blk < 140) {
        // ------------------- R rows with inline Weff -------------------
        const int graph = (blk >= 80);
        const int rel   = graph ? blk - 80 : blk;
        const int u     = rel / 5;
        const int tpg   = rel % 5;
        const int V     = graph ? 12 : 16;
        const int K     = graph ? 300 : 400;
        const int KP    = graph ? 320 : 448;
        const float* wt = graph ? wt_err : wt_ecc;
        const float* W0 = graph ? W0_err : W0_ecc;
        const float* W1 = graph ? W1_err : W1_ecc;
        const float* Wp = graph ? Wp_err : Wp_ecc;
        char* B = (char*)(graph ? g_B_err : g_B_ecc);

        __shared__ float wts[96];
        __shared__ float w0s[5 * 64];
        __shared__ float w1s[5 * 64];
        if (t < 96) wts[t] = wt[t];
        __syncthreads();

        for (int idx = t; idx < 320; idx += 256) {
            const int j = idx >> 6, g = idx & 63;
            const int tp = tpg * 5 + j;
            float s0 = 0.f, s1 = 0.f;
            #pragma unroll 4
            for (int c = 0; c < 32; c++) {
                #pragma unroll
                for (int k = 0; k < 3; k++) {
                    const int tt = tp - k + 1;
                    if (tt >= 0 && tt < 25) {
                        const float w = wts[c * 3 + k];
                        s0 = fmaf(w, W0[(c * 25 + tt) * 64 + g], s0);
                        s1 = fmaf(w, W1[(c * 25 + tt) * 64 + g], s1);
                    }
                }
            }
            w0s[idx] = s0;
            w1s[idx] = -0.5f * s1;
        }
        __syncthreads();

        const int h  = t;                 // output column n
        const int up = (u + 1) % V;
        const int um = (u + V - 1) % V;

        float acc[5] = {0.f, 0.f, 0.f, 0.f, 0.f};
        const float* WpU = Wp + (size_t)(u  * 64) * 256 + h;
        const float* WpP = Wp + (size_t)(up * 64) * 256 + h;
        const float* WpM = Wp + (size_t)(um * 64) * 256 + h;

        #pragma unroll 4
        for (int gg = 0; gg < 64; gg++) {
            const float wp_u = WpU[gg * 256];
            const float wp_s = WpP[gg * 256] + WpM[gg * 256];
            #pragma unroll
            for (int j = 0; j < 5; j++) {
                acc[j] = fmaf(w0s[j * 64 + gg], wp_u, acc[j]);
                acc[j] = fmaf(w1s[j * 64 + gg], wp_s, acc[j]);
            }
        }

        #pragma unroll
        for (int j = 0; j < 5; j++) {
            const int k = u * 25 + tpg * 5 + j;
            const int c = k >> 6, kk = k & 63;
            const uint32_t off = SWZ((uint32_t)(h * 128 + kk * 2));
            *(__half*)(B + (size_t)c * 32768 + off) = __float2half(acc[j]);
        }
        if (u == 0 && tpg == 0) {
            for (int k = K; k < KP; k++) {
                const int c = k >> 6, kk = k & 63;
                const uint32_t off = SWZ((uint32_t)(h * 128 + kk * 2));
                *(__half*)(B + (size_t)c * 32768 + off) =
                    __ushort_as_half((unsigned short)0);
            }
        }
    } else if (blk < 168) {
        // ------------------- c0 + bias_part -------------------
        const int rel   = blk - 140;
        const int graph = (rel >= 16);
        const int u     = graph ? rel - 16 : rel;
        const float* bt = graph ? bt_err : bt_ecc;
        const float* W0 = graph ? W0_err : W0_ecc;
        const float* W1 = graph ? W1_err : W1_ecc;
        const float* bb = graph ? b_err  : b_ecc;
        const float* Wp = graph ? Wp_err : Wp_ecc;
        const float* bp = graph ? bp_err : bp_ecc;

        __shared__ float part[256];
        __shared__ float c0s[64];

        const int g = t & 63, cb = (t >> 6) * 8;
        float s = 0.f;
        #pragma unroll
        for (int ci = 0; ci < 8; ci++) {
            const int c = cb + ci;
            float a = 0.f;
            #pragma unroll
            for (int tt = 0; tt < 25; tt++)
                a += W0[(c * 25 + tt) * 64 + g] - W1[(c * 25 + tt) * 64 + g];
            s = fmaf(bt[c], a, s);
        }
        part[t] = s;
        __syncthreads();
        if (t < 64)
            c0s[g] = part[g] + part[64 + g] + part[128 + g] + part[192 + g] + bb[g];
        __syncthreads();

        const int h = t;
        float pbias = (u == 0) ? bp[h] : 0.f;
        const float* WpU = Wp + (size_t)(u * 64) * 256 + h;
        #pragma unroll 8
        for (int gg = 0; gg < 64; gg++)
            pbias = fmaf(c0s[gg], WpU[gg * 256], pbias);
        g_bias_part[((graph ? 16 : 0) + u) * 256 + h] = pbias;
    } else if (blk == 168) {
        // ------------------- We^T fp16 -------------------
        for (int i = t; i < 4096; i += 256) {
            const int n = i >> 6, k = i & 63;
            g_WeT[n * 64 + k] = __float2half(We[k * 64 + n]);
        }
    } else if (blk < 425) {
        // ------------------- ecc -> chunked swizzled fp16 -------------------
        const int r0 = (blk - 169) * 32;
        char* dstb = (char*)g_A_ecc;
        for (int idx = t; idx < 32 * 56; idx += 256) {
            const int row = idx / 56, gg = idx - row * 56;
            const int r = r0 + row;
            uint4 v = make_uint4(0u, 0u, 0u, 0u);
            if (gg < 50) {
                const float* s = ecc + (size_t)r * 400 + gg * 8;
                const float4 a = *(const float4*)s;
                const float4 b = *(const float4*)(s + 4);
                v.x = pack_hi16(a.x, a.y); v.y = pack_hi16(a.z, a.w);
                v.z = pack_hi16(b.x, b.y); v.w = pack_hi16(b.z, b.w);
            }
            const int c = gg >> 3, gq = gg & 7;
            const uint32_t off = SWZ((uint32_t)((r & 63) * 128 + gq * 16));
            *(uint4*)(dstb + (size_t)(r >> 6) * A_TILE_ECC + c * 8192 + off) = v;
        }
    } else if (blk < 681) {
        // ------------------- err -> chunked swizzled fp16 -------------------
        const int r0 = (blk - 425) * 32;
        char* dstb = (char*)g_A_err;
        for (int idx = t; idx < 32 * 40; idx += 256) {
            const int row = idx / 40, gg = idx - row * 40;
            const int r = r0 + row;
            uint4 v = make_uint4(0u, 0u, 0u, 0u);
            if (gg < 37) {
                const float* s = err + (size_t)r * 300 + gg * 8;
                const float4 a = *(const float4*)s;
                const float4 b = *(const float4*)(s + 4);
                v.x = pack_hi16(a.x, a.y); v.y = pack_hi16(a.z, a.w);
                v.z = pack_hi16(b.x, b.y); v.w = pack_hi16(b.z, b.w);
            } else if (gg == 37) {
                const float* s = err + (size_t)r * 300 + 296;
                v.x = pack_hi16(s[0], s[1]); v.y = pack_hi16(s[2], s[3]);
            }
            const int c = gg >> 3, gq = gg & 7;
            const uint32_t off = SWZ((uint32_t)((r & 63) * 128 + gq * 16));
            *(uint4*)(dstb + (size_t)(r >> 6) * A_TILE_ERR + c * 8192 + off) = v;
        }
    } else {
        // ------------------- ehr -> fp16 (row-major, swizzled at use) -------
        const int r0 = (blk - 681) * 128;
        for (int idx = t; idx < 128 * 8; idx += 256) {
            const int row = idx >> 3, gg = idx & 7;
            const float* s = ehr + (size_t)(r0 + row) * 64 + gg * 8;
            const float4 a = *(const float4*)s;
            const float4 b = *(const float4*)(s + 4);
            uint4 v;
            v.x = pack_hi16(a.x, a.y); v.y = pack_hi16(a.z, a.w);
            v.z = pack_hi16(b.x, b.y); v.w = pack_hi16(b.z, b.w);
            *(uint4*)(g_Ah_ehr + (size_t)(r0 + row) * 64 + gg * 8) = v;
        }
    }
}

// ============================================================================
// K2: FUSED GEMM + ehr-MMA + epilogue, cp.async.bulk staging.
// 128 blocks x 64 batch rows; 256 thr (8 warps, 32x64 warp tiles).
// 12 global chunks (7 ecc + 5 err), 3 stages, mbarrier per stage.
// ============================================================================
#define A_OFF        0
#define B_OFF        8192
#define STAGE_SZ     40960
#define EHRP_OFF     40960
#define STASH_E_OFF  122880
#define STASH_STRIDE 264
#define STASH_R_OFF  156672
#define BIAS_E_OFF   190464
#define BIAS_R_OFF   191488
#define MBAR_OFF     192512
#define FUSED_SMEM   192576

__global__ __launch_bounds__(256, 1) void fused_kernel(
    const float* __restrict__ Wa, const float* __restrict__ ba,
    const float* __restrict__ be,
    const float* __restrict__ Wf2, const float* __restrict__ bf2,
    float* __restrict__ out)
{
    extern __shared__ char dsm[];
    const uint32_t sb = smem_to_u32(dsm);
    const int tid = threadIdx.x, lane = tid & 31, wid = tid >> 5;
    const int bm = blockIdx.x;

    // ---- init mbarriers ----
    if (tid == 0) {
        MBARRIER_INIT(sb + MBAR_OFF,      1);
        MBARRIER_INIT(sb + MBAR_OFF + 8,  1);
        MBARRIER_INIT(sb + MBAR_OFF + 16, 1);
    }

    // ---- bias sums ----
    {
        float s = 0.f;
        #pragma unroll
        for (int u = 0; u < 16; u++) s += g_bias_part[u * 256 + tid];
        ((float*)(dsm + BIAS_E_OFF))[tid] = s;
        s = 0.f;
        #pragma unroll
        for (int u = 0; u < 12; u++) s += g_bias_part[(16 + u) * 256 + tid];
        ((float*)(dsm + BIAS_R_OFF))[tid] = s;
    }
    __syncthreads();   // mbar init + bias visible

    const int warp_m = wid & 1, warp_n = wid >> 1;
    const int sub = lane >> 3, i8 = lane & 7;

    // global chunk cc in [0,12): graph = cc>=7, local chunk = cc or cc-7
    auto issue = [&](int cc) {
        const uint32_t mbar = sb + MBAR_OFF + (cc % 3) * 8;
        const uint32_t base = sb + (cc % 3) * STAGE_SZ;
        const char* aSrc;
        const char* bSrc;
        if (cc < 7) {
            aSrc = (const char*)g_A_ecc + (size_t)bm * A_TILE_ECC + cc * 8192;
            bSrc = (const char*)g_B_ecc + (size_t)cc * 32768;
        } else {
            aSrc = (const char*)g_A_err + (size_t)bm * A_TILE_ERR + (cc - 7) * 8192;
            bSrc = (const char*)g_B_err + (size_t)(cc - 7) * 32768;
        }
        MBARRIER_EXPECT_TX(mbar, 40960u);
        CP_BULK(base + A_OFF, aSrc, 8192u, mbar);
        CP_BULK(base + B_OFF, bSrc, 32768u, mbar);
    };

    if (tid == 0) { issue(0); issue(1); }

    for (int graph = 0; graph < 2; graph++) {
        const int NC = graph ? 5 : 7;
        __half* stash = (__half*)(dsm + (graph ? STASH_R_OFF : STASH_E_OFF));
        const float* bias_s =
            (const float*)(dsm + (graph ? BIAS_R_OFF : BIAS_E_OFF));

        float acc[2][8][4];
        #pragma unroll
        for (int mi = 0; mi < 2; mi++)
            #pragma unroll
            for (int ni = 0; ni < 8; ni++)
                #pragma unroll
                for (int q = 0; q < 4; q++) acc[mi][ni][q] = 0.f;

        for (int c = 0; c < NC; c++) {
            const int cc = graph ? 7 + c : c;
            MBARRIER_WAIT_PARITY(sb + MBAR_OFF + (cc % 3) * 8, (cc / 3) & 1);
            __syncthreads();            // all warps done with chunk cc-1
            if (tid == 0 && cc + 2 < 12) issue(cc + 2);

            const uint32_t base = sb + (cc % 3) * STAGE_SZ;
            #pragma unroll
            for (int ks = 0; ks < 4; ks++) {
                uint32_t ah[2][4];
                #pragma unroll
                for (int mi = 0; mi < 2; mi++) {
                    const int ar = warp_m * 32 + mi * 16 + i8 + (sub & 1) * 8;
                    const int akg = ks * 2 + (sub >> 1);
                    const uint32_t off =
                        (uint32_t)(ar * 64 + ((akg ^ (ar & 7)) * 8)) * 2u;
                    LDSM_X4(ah[mi][0], ah[mi][1], ah[mi][2], ah[mi][3],
                            base + A_OFF + off);
                }
                #pragma unroll
                for (int p = 0; p < 4; p++) {
                    const int nn = warp_n * 64 + p * 16 + i8 + (sub >> 1) * 8;
                    const int bkg = ks * 2 + (sub & 1);
                    const uint32_t off =
                        (uint32_t)(nn * 64 + ((bkg ^ (nn & 7)) * 8)) * 2u;
                    uint32_t b0, b1, b2, b3;
                    LDSM_X4(b0, b1, b2, b3, base + B_OFF + off);
                    #pragma unroll
                    for (int mi = 0; mi < 2; mi++) {
                        MMA16816(acc[mi][2 * p],     ah[mi], b0, b1);
                        MMA16816(acc[mi][2 * p + 1], ah[mi], b2, b3);
                    }
                }
            }
        }

        // writeback to fp16 stash (+bias); stash disjoint from stages
        const int g8 = lane >> 2, tg = lane & 3;
        #pragma unroll
        for (int mi = 0; mi < 2; mi++) {
            const int row0 = warp_m * 32 + mi * 16 + g8;
            #pragma unroll
            for (int ni = 0; ni < 8; ni++) {
                const int col = warp_n * 64 + ni * 8 + tg * 2;
                const float b0 = bias_s[col], b1 = bias_s[col + 1];
                *(__half2*)(stash + row0 * STASH_STRIDE + col) =
                    __floats2half2_rn(acc[mi][ni][0] + b0, acc[mi][ni][1] + b1);
                *(__half2*)(stash + (row0 + 8) * STASH_STRIDE + col) =
                    __floats2half2_rn(acc[mi][ni][2] + b0, acc[mi][ni][3] + b1);
            }
        }
    }
    __syncthreads();   // stashes settled; stages free

    // ---- ehr mini-GEMM: ehrp = relu(ehr @ We + be) ----
    {
        #pragma unroll
        for (int it = 0; it < 2; it++) {
            const int idx = tid + it * 256;
            const int row = idx >> 3, g = idx & 7;
            const __half* src = g_Ah_ehr + (size_t)(bm * 64 + row) * 64 + g * 8;
            const uint32_t off = (uint32_t)(row * 8 + (g ^ (row & 7))) * 16u;
            CP_ASYNC16(sb + A_OFF + off, (const void*)src);
        }
        #pragma unroll
        for (int it = 0; it < 2; it++) {
            const int idx = tid + it * 256;
            const int row = idx >> 3, g = idx & 7;
            const __half* src = g_WeT + (size_t)row * 64 + g * 8;
            const uint32_t off = (uint32_t)(row * 8 + (g ^ (row & 7))) * 16u;
            CP_ASYNC16(sb + B_OFF + off, (const void*)src);
        }
        CP_COMMIT();
        CP_WAIT0();
        __syncthreads();

        float accH[2][2][4];
        #pragma unroll
        for (int mi = 0; mi < 2; mi++)
            #pragma unroll
            for (int ni = 0; ni < 2; ni++)
                #pragma unroll
                for (int q = 0; q < 4; q++) accH[mi][ni][q] = 0.f;

        #pragma unroll
        for (int ks = 0; ks < 4; ks++) {
            uint32_t ah[2][4];
            #pragma unroll
            for (int mi = 0; mi < 2; mi++) {
                const int ar = warp_m * 32 + mi * 16 + i8 + (sub & 1) * 8;
                const int akg = ks * 2 + (sub >> 1);
                const uint32_t off =
                    (uint32_t)(ar * 64 + ((akg ^ (ar & 7)) * 8)) * 2u;
                LDSM_X4(ah[mi][0], ah[mi][1], ah[mi][2], ah[mi][3],
                        sb + A_OFF + off);
            }
            const int nn = warp_n * 16 + i8 + (sub >> 1) * 8;
            const int bkg = ks * 2 + (sub & 1);
            const uint32_t off =
                (uint32_t)(nn * 64 + ((bkg ^ (nn & 7)) * 8)) * 2u;
            uint32_t b0, b1, b2, b3;
            LDSM_X4(b0, b1, b2, b3, sb + B_OFF + off);
            #pragma unroll
            for (int mi = 0; mi < 2; mi++) {
                MMA16816(accH[mi][0], ah[mi], b0, b1);
                MMA16816(accH[mi][1], ah[mi], b2, b3);
            }
        }

        float* ehrp = (float*)(dsm + EHRP_OFF);
        const int g8 = lane >> 2, tg = lane & 3;
        #pragma unroll
        for (int mi = 0; mi < 2; mi++) {
            const int row0 = warp_m * 32 + mi * 16 + g8;
            #pragma unroll
            for (int ni = 0; ni < 2; ni++) {
                const int col = warp_n * 16 + ni * 8 + tg * 2;
                const float b0 = __ldg(be + col), b1 = __ldg(be + col + 1);
                ehrp[row0 * 64 + col]       = fmaxf(accH[mi][ni][0] + b0, 0.f);
                ehrp[row0 * 64 + col + 1]   = fmaxf(accH[mi][ni][1] + b1, 0.f);
                ehrp[(row0 + 8) * 64 + col] = fmaxf(accH[mi][ni][2] + b0, 0.f);
                ehrp[(row0 + 8) * 64 + col + 1] =
                    fmaxf(accH[mi][ni][3] + b1, 0.f);
            }
        }
    }
    __syncthreads();

    // ---- epilogue (warp-per-row, all from smem) ----
    const __half* stash_e = (const __half*)(dsm + STASH_E_OFF);
    const __half* stash_r = (const __half*)(dsm + STASH_R_OFF);
    const float* ehrp     = (const float*)(dsm + EHRP_OFF);
    const float ba0 = ba[0], bf0 = bf2[0];
    float wa[8], wf[8];
    #pragma unroll
    for (int j = 0; j < 8; j++) {
        wa[j] = Wa[lane + 32 * j];
        wf[j] = Wf2[lane + 32 * j];
    }
    const float wfe0 = Wf2[256 + lane], wfe1 = Wf2[256 + lane + 32];

    #pragma unroll 2
    for (int q = 0; q < 8; q++) {
        const int row = wid * 8 + q;
        float e[8], r[8];
        #pragma unroll
        for (int j = 0; j < 8; j++) {
            e[j] = __half2float(stash_e[row * STASH_STRIDE + lane + 32 * j]);
            r[j] = __half2float(stash_r[row * STASH_STRIDE + lane + 32 * j]);
        }
        const float o0 = ehrp[row * 64 + lane];
        const float o1 = ehrp[row * 64 + lane + 32];

        float s = 0.f;
        #pragma unroll
        for (int j = 0; j < 8; j++)
            s = fmaf(tanh_fast(e[j] + r[j]), wa[j], s);
        #pragma unroll
        for (int off = 16; off > 0; off >>= 1)
            s += __shfl_xor_sync(0xffffffffu, s, off);
        const float attn = 1.f / (1.f + __expf(-(s + ba0)));

        float v = o0 * wfe0 + o1 * wfe1;
        #pragma unroll
        for (int j = 0; j < 8; j++) {
            const float f = attn * e[j] + (1.f - attn) * r[j];
            v = fmaf(fmaxf(f, 0.f), wf[j], v);
        }
        #pragma unroll
        for (int off = 16; off > 0; off >>= 1)
            v += __shfl_xor_sync(0xffffffffu, v, off);
        if (lane == 0)
            out[bm * 64 + row] = 1.f / (1.f + __expf(-(v + bf0)));
    }
}

// ============================================================================
extern "C" void kernel_launch(void* const* d_in, const int* in_sizes, int n_in,
                              void* d_out, int out_size) {
    const float* ecc    = (const float*)d_in[0];
    const float* err    = (const float*)d_in[1];
    const float* ehr    = (const float*)d_in[2];
    const float* wt_ecc = (const float*)d_in[3];
    const float* bt_ecc = (const float*)d_in[4];
    const float* wt_err = (const float*)d_in[5];
    const float* bt_err = (const float*)d_in[6];
    const float* W0_ecc = (const float*)d_in[7];
    const float* W1_ecc = (const float*)d_in[8];
    const float* b_ecc  = (const float*)d_in[9];
    const float* W0_err = (const float*)d_in[10];
    const float* W1_err = (const float*)d_in[11];
    const float* b_err  = (const float*)d_in[12];
    const float* Wp_ecc = (const float*)d_in[13];
    const float* bp_ecc = (const float*)d_in[14];
    const float* Wp_err = (const float*)d_in[15];
    const float* bp_err = (const float*)d_in[16];
    const float* Wa     = (const float*)d_in[17];
    const float* ba     = (const float*)d_in[18];
    const float* We     = (const float*)d_in[19];
    const float* be     = (const float*)d_in[20];
    const float* Wf2    = (const float*)d_in[21];
    const float* bf2    = (const float*)d_in[22];

    cudaFuncSetAttribute(fused_kernel,
                         cudaFuncAttributeMaxDynamicSharedMemorySize, FUSED_SMEM);

    precompute<<<745, 256>>>(ecc, err, ehr,
                             wt_ecc, bt_ecc, wt_err, bt_err,
                             W0_ecc, W1_ecc, b_ecc, W0_err, W1_err, b_err,
                             Wp_ecc, bp_ecc, Wp_err, bp_err, We);
    fused_kernel<<<128, 256, FUSED_SMEM>>>(Wa, ba, be, Wf2, bf2,
                                           (float*)d_out);
}

// round 14
// speedup vs baseline: 1.0109x; 1.0109x over previous
#include <cuda_runtime.h>
#include <cuda_fp16.h>
#include <math.h>
#include <stdint.h>

#define B_TOT 8192

// ecc: NC=7 chunks of K=64; A tile/chunk image 8KB, tile total 57344 B.
// err: NC=5; tile total 40960 B. B images: 32KB per chunk.
#define A_TILE_ECC 57344
#define A_TILE_ERR 40960

// ============================================================================
// Device globals (A and B stored as PRE-SWIZZLED chunk-major smem images)
// ============================================================================
__device__ __align__(16) __half g_B_ecc[7 * 16384];    // 7 chunks x 32KB
__device__ __align__(16) __half g_B_err[5 * 16384];
__device__ __align__(16) __half g_A_ecc[B_TOT * 448];  // [tile][chunk][img]
__device__ __align__(16) __half g_A_err[B_TOT * 320];
__device__ __align__(16) __half g_WeT[64 * 64];        // We^T fp16 [n][k]
__device__ __align__(16) __half g_Ah_ehr[B_TOT * 64];
__device__ float g_bias_part[28 * 256];

// ---------------------------------------------------------------------------
#define MMA16816(d, a, b0_, b1_) \
    asm volatile( \
        "mma.sync.aligned.m16n8k16.row.col.f32.f16.f16.f32 " \
        "{%0,%1,%2,%3}, {%4,%5,%6,%7}, {%8,%9}, {%0,%1,%2,%3};" \
        : "+f"((d)[0]), "+f"((d)[1]), "+f"((d)[2]), "+f"((d)[3]) \
        : "r"((a)[0]), "r"((a)[1]), "r"((a)[2]), "r"((a)[3]), \
          "r"(b0_), "r"(b1_))

#define LDSM_X4(r0, r1, r2, r3, addr) \
    asm volatile( \
        "ldmatrix.sync.aligned.m8n8.x4.shared.b16 {%0,%1,%2,%3}, [%4];" \
        : "=r"(r0), "=r"(r1), "=r"(r2), "=r"(r3) : "r"(addr))

#define CP_ASYNC16(dst, src) \
    asm volatile("cp.async.cg.shared.global [%0], [%1], 16;" \
        :: "r"(dst), "l"(src) : "memory")
#define CP_COMMIT() asm volatile("cp.async.commit_group;" ::: "memory")
#define CP_WAIT0()  asm volatile("cp.async.wait_group 0;" ::: "memory")

#define CP_BULK(dst, src, bytes, mbar) \
    asm volatile( \
        "cp.async.bulk.shared::cta.global.mbarrier::complete_tx::bytes " \
        "[%0], [%1], %2, [%3];" \
        :: "r"(dst), "l"(src), "r"(bytes), "r"(mbar) : "memory")

#define MBARRIER_INIT(mbar, count) \
    asm volatile("mbarrier.init.shared.b64 [%0], %1;" \
        :: "r"((uint32_t)(mbar)), "r"((uint32_t)(count)) : "memory")
#define MBARRIER_EXPECT_TX(mbar, bytes) \
    asm volatile("mbarrier.arrive.expect_tx.shared.b64 _, [%0], %1;" \
        :: "r"((uint32_t)(mbar)), "r"((uint32_t)(bytes)) : "memory")
#define MBARRIER_WAIT_PARITY(mbar_addr, phase_parity) do { \
    uint32_t _mbar = (uint32_t)(mbar_addr); \
    uint32_t _parity = (uint32_t)(phase_parity); \
    uint32_t _done; \
    asm volatile( \
        "{\n\t.reg .pred p;\n\t" \
        "mbarrier.try_wait.parity.acquire.cta.shared::cta.b64 p, [%1], %2;\n\t" \
        "selp.b32 %0, 1, 0, p;\n\t}" \
        : "=r"(_done) : "r"(_mbar), "r"(_parity) : "memory"); \
    if (!_done) { \
        asm volatile( \
            "{\n\t.reg .pred P1;\n\t" \
            "WAIT_LOOP_%=:\n\t" \
            "mbarrier.try_wait.parity.acquire.cta.shared::cta.b64 P1, [%0], %1, 0x989680;\n\t" \
            "@P1 bra.uni WAIT_DONE_%=;\n\t" \
            "bra.uni WAIT_LOOP_%=;\n\t" \
            "WAIT_DONE_%=:\n\t}" \
            :: "r"(_mbar), "r"(_parity) : "memory"); \
    } \
} while(0)

#define SWZ(off) ((off) ^ (((off) >> 3) & 0x70))

__device__ __forceinline__ uint32_t smem_to_u32(const void* p) {
    uint32_t a;
    asm("{ .reg .u64 t; cvta.to.shared.u64 t, %1; cvt.u32.u64 %0, t; }"
        : "=r"(a) : "l"(p));
    return a;
}
__device__ __forceinline__ uint32_t pack_hi16(float a, float b) {
    return (uint32_t)__half_as_ushort(__float2half(a)) |
           ((uint32_t)__half_as_ushort(__float2half(b)) << 16);
}
__device__ __forceinline__ float tanh_fast(float x) {
    float y;
    asm("tanh.approx.f32 %0, %1;" : "=f"(y) : "f"(x));
    return y;
}

// ============================================================================
// K1: merged precompute + fp16 conversions (chunk-major pre-swizzled images).
// Conversion loops iterate CHUNK-MAJOR so consecutive threads write
// consecutive 16B granules of one 128B row (fixes R13's 8x store scatter).
//  0..139   : R rows (Weff inline) -> g_B_* images
//  140..167 : c0 + bias_part       168: We^T
//  169..424 : ecc -> images (32 rows/blk)   425..680: err (32 rows/blk)
//  681..744 : ehr -> fp16 (128 rows/blk)
// ============================================================================
__global__ __launch_bounds__(256) void precompute(
    const float* __restrict__ ecc, const float* __restrict__ err,
    const float* __restrict__ ehr,
    const float* __restrict__ wt_ecc, const float* __restrict__ bt_ecc,
    const float* __restrict__ wt_err, const float* __restrict__ bt_err,
    const float* __restrict__ W0_ecc, const float* __restrict__ W1_ecc,
    const float* __restrict__ b_ecc,
    const float* __restrict__ W0_err, const float* __restrict__ W1_err,
    const float* __restrict__ b_err,
    const float* __restrict__ Wp_ecc, const float* __restrict__ bp_ecc,
    const float* __restrict__ Wp_err, const float* __restrict__ bp_err,
    const float* __restrict__ We)
{
    const int blk = blockIdx.x;
    const int t   = threadIdx.x;

    if (blk < 140) {
        // ------------------- R rows with inline Weff -------------------
        const int graph = (blk >= 80);
        const int rel   = graph ? blk - 80 : blk;
        const int u     = rel / 5;
        const int tpg   = rel % 5;
        const int V     = graph ? 12 : 16;
        const int K     = graph ? 300 : 400;
        const int KP    = graph ? 320 : 448;
        const float* wt = graph ? wt_err : wt_ecc;
        const float* W0 = graph ? W0_err : W0_ecc;
        const float* W1 = graph ? W1_err : W1_ecc;
        const float* Wp = graph ? Wp_err : Wp_ecc;
        char* B = (char*)(graph ? g_B_err : g_B_ecc);

        __shared__ float wts[96];
        __shared__ float w0s[5 * 64];
        __shared__ float w1s[5 * 64];
        if (t < 96) wts[t] = wt[t];
        __syncthreads();

        for (int idx = t; idx < 320; idx += 256) {
            const int j = idx >> 6, g = idx & 63;
            const int tp = tpg * 5 + j;
            float s0 = 0.f, s1 = 0.f;
            #pragma unroll 4
            for (int c = 0; c < 32; c++) {
                #pragma unroll
                for (int k = 0; k < 3; k++) {
                    const int tt = tp - k + 1;
                    if (tt >= 0 && tt < 25) {
                        const float w = wts[c * 3 + k];
                        s0 = fmaf(w, W0[(c * 25 + tt) * 64 + g], s0);
                        s1 = fmaf(w, W1[(c * 25 + tt) * 64 + g], s1);
                    }
                }
            }
            w0s[idx] = s0;
            w1s[idx] = -0.5f * s1;
        }
        __syncthreads();

        const int h  = t;                 // output column n
        const int up = (u + 1) % V;
        const int um = (u + V - 1) % V;

        float acc[5] = {0.f, 0.f, 0.f, 0.f, 0.f};
        const float* WpU = Wp + (size_t)(u  * 64) * 256 + h;
        const float* WpP = Wp + (size_t)(up * 64) * 256 + h;
        const float* WpM = Wp + (size_t)(um * 64) * 256 + h;

        #pragma unroll 4
        for (int gg = 0; gg < 64; gg++) {
            const float wp_u = WpU[gg * 256];
            const float wp_s = WpP[gg * 256] + WpM[gg * 256];
            #pragma unroll
            for (int j = 0; j < 5; j++) {
                acc[j] = fmaf(w0s[j * 64 + gg], wp_u, acc[j]);
                acc[j] = fmaf(w1s[j * 64 + gg], wp_s, acc[j]);
            }
        }

        #pragma unroll
        for (int j = 0; j < 5; j++) {
            const int k = u * 25 + tpg * 5 + j;
            const int c = k >> 6, kk = k & 63;
            const uint32_t off = SWZ((uint32_t)(h * 128 + kk * 2));
            *(__half*)(B + (size_t)c * 32768 + off) = __float2half(acc[j]);
        }
        if (u == 0 && tpg == 0) {
            for (int k = K; k < KP; k++) {
                const int c = k >> 6, kk = k & 63;
                const uint32_t off = SWZ((uint32_t)(h * 128 + kk * 2));
                *(__half*)(B + (size_t)c * 32768 + off) =
                    __ushort_as_half((unsigned short)0);
            }
        }
    } else if (blk < 168) {
        // ------------------- c0 + bias_part -------------------
        const int rel   = blk - 140;
        const int graph = (rel >= 16);
        const int u     = graph ? rel - 16 : rel;
        const float* bt = graph ? bt_err : bt_ecc;
        const float* W0 = graph ? W0_err : W0_ecc;
        const float* W1 = graph ? W1_err : W1_ecc;
        const float* bb = graph ? b_err  : b_ecc;
        const float* Wp = graph ? Wp_err : Wp_ecc;
        const float* bp = graph ? bp_err : bp_ecc;

        __shared__ float part[256];
        __shared__ float c0s[64];

        const int g = t & 63, cb = (t >> 6) * 8;
        float s = 0.f;
        #pragma unroll
        for (int ci = 0; ci < 8; ci++) {
            const int c = cb + ci;
            float a = 0.f;
            #pragma unroll
            for (int tt = 0; tt < 25; tt++)
                a += W0[(c * 25 + tt) * 64 + g] - W1[(c * 25 + tt) * 64 + g];
            s = fmaf(bt[c], a, s);
        }
        part[t] = s;
        __syncthreads();
        if (t < 64)
            c0s[g] = part[g] + part[64 + g] + part[128 + g] + part[192 + g] + bb[g];
        __syncthreads();

        const int h = t;
        float pbias = (u == 0) ? bp[h] : 0.f;
        const float* WpU = Wp + (size_t)(u * 64) * 256 + h;
        #pragma unroll 8
        for (int gg = 0; gg < 64; gg++)
            pbias = fmaf(c0s[gg], WpU[gg * 256], pbias);
        g_bias_part[((graph ? 16 : 0) + u) * 256 + h] = pbias;
    } else if (blk == 168) {
        // ------------------- We^T fp16 -------------------
        for (int i = t; i < 4096; i += 256) {
            const int n = i >> 6, k = i & 63;
            g_WeT[n * 64 + k] = __float2half(We[k * 64 + n]);
        }
    } else if (blk < 425) {
        // ------ ecc -> chunked swizzled fp16, CHUNK-MAJOR loop ------
        const int r0 = (blk - 169) * 32;
        char* dstb = (char*)g_A_ecc;
        // 7 chunks x 32 rows x 8 granules = 1792 16B writes, coalesced
        for (int w = t; w < 1792; w += 256) {
            const int c   = w >> 8;          // chunk
            const int rem = w & 255;
            const int row = rem >> 3;
            const int gq  = rem & 7;
            const int gg  = c * 8 + gq;
            const int r   = r0 + row;
            uint4 v = make_uint4(0u, 0u, 0u, 0u);
            if (gg < 50) {
                const float* s = ecc + (size_t)r * 400 + gg * 8;
                const float4 a = *(const float4*)s;
                const float4 b = *(const float4*)(s + 4);
                v.x = pack_hi16(a.x, a.y); v.y = pack_hi16(a.z, a.w);
                v.z = pack_hi16(b.x, b.y); v.w = pack_hi16(b.z, b.w);
            }
            const uint32_t off = SWZ((uint32_t)((r & 63) * 128 + gq * 16));
            *(uint4*)(dstb + (size_t)(r >> 6) * A_TILE_ECC + c * 8192 + off) = v;
        }
    } else if (blk < 681) {
        // ------ err -> chunked swizzled fp16, CHUNK-MAJOR loop ------
        const int r0 = (blk - 425) * 32;
        char* dstb = (char*)g_A_err;
        // 5 chunks x 32 rows x 8 granules = 1280 16B writes
        for (int w = t; w < 1280; w += 256) {
            const int c   = w >> 8;
            const int rem = w & 255;
            const int row = rem >> 3;
            const int gq  = rem & 7;
            const int gg  = c * 8 + gq;
            const int r   = r0 + row;
            uint4 v = make_uint4(0u, 0u, 0u, 0u);
            if (gg < 37) {
                const float* s = err + (size_t)r * 300 + gg * 8;
                const float4 a = *(const float4*)s;
                const float4 b = *(const float4*)(s + 4);
                v.x = pack_hi16(a.x, a.y); v.y = pack_hi16(a.z, a.w);
                v.z = pack_hi16(b.x, b.y); v.w = pack_hi16(b.z, b.w);
            } else if (gg == 37) {
                const float* s = err + (size_t)r * 300 + 296;
                v.x = pack_hi16(s[0], s[1]); v.y = pack_hi16(s[2], s[3]);
            }
            const uint32_t off = SWZ((uint32_t)((r & 63) * 128 + gq * 16));
            *(uint4*)(dstb + (size_t)(r >> 6) * A_TILE_ERR + c * 8192 + off) = v;
        }
    } else {
        // ------------------- ehr -> fp16 -------------------
        const int r0 = (blk - 681) * 128;
        for (int idx = t; idx < 128 * 8; idx += 256) {
            const int row = idx >> 3, gg = idx & 7;
            const float* s = ehr + (size_t)(r0 + row) * 64 + gg * 8;
            const float4 a = *(const float4*)s;
            const float4 b = *(const float4*)(s + 4);
            uint4 v;
            v.x = pack_hi16(a.x, a.y); v.y = pack_hi16(a.z, a.w);
            v.z = pack_hi16(b.x, b.y); v.w = pack_hi16(b.z, b.w);
            *(uint4*)(g_Ah_ehr + (size_t)(r0 + row) * 64 + gg * 8) = v;
        }
    }
}

// ============================================================================
// K2: FUSED GEMM + ehr-MMA + epilogue, cp.async.bulk staging (unchanged
// from R13 — it improved 22.1 -> 20.3us).
// ============================================================================
#define A_OFF        0
#define B_OFF        8192
#define STAGE_SZ     40960
#define EHRP_OFF     40960
#define STASH_E_OFF  122880
#define STASH_STRIDE 264
#define STASH_R_OFF  156672
#define BIAS_E_OFF   190464
#define BIAS_R_OFF   191488
#define MBAR_OFF     192512
#define FUSED_SMEM   192576

__global__ __launch_bounds__(256, 1) void fused_kernel(
    const float* __restrict__ Wa, const float* __restrict__ ba,
    const float* __restrict__ be,
    const float* __restrict__ Wf2, const float* __restrict__ bf2,
    float* __restrict__ out)
{
    extern __shared__ char dsm[];
    const uint32_t sb = smem_to_u32(dsm);
    const int tid = threadIdx.x, lane = tid & 31, wid = tid >> 5;
    const int bm = blockIdx.x;

    if (tid == 0) {
        MBARRIER_INIT(sb + MBAR_OFF,      1);
        MBARRIER_INIT(sb + MBAR_OFF + 8,  1);
        MBARRIER_INIT(sb + MBAR_OFF + 16, 1);
    }

    {
        float s = 0.f;
        #pragma unroll
        for (int u = 0; u < 16; u++) s += g_bias_part[u * 256 + tid];
        ((float*)(dsm + BIAS_E_OFF))[tid] = s;
        s = 0.f;
        #pragma unroll
        for (int u = 0; u < 12; u++) s += g_bias_part[(16 + u) * 256 + tid];
        ((float*)(dsm + BIAS_R_OFF))[tid] = s;
    }
    __syncthreads();

    const int warp_m = wid & 1, warp_n = wid >> 1;
    const int sub = lane >> 3, i8 = lane & 7;

    auto issue = [&](int cc) {
        const uint32_t mbar = sb + MBAR_OFF + (cc % 3) * 8;
        const uint32_t base = sb + (cc % 3) * STAGE_SZ;
        const char* aSrc;
        const char* bSrc;
        if (cc < 7) {
            aSrc = (const char*)g_A_ecc + (size_t)bm * A_TILE_ECC + cc * 8192;
            bSrc = (const char*)g_B_ecc + (size_t)cc * 32768;
        } else {
            aSrc = (const char*)g_A_err + (size_t)bm * A_TILE_ERR + (cc - 7) * 8192;
            bSrc = (const char*)g_B_err + (size_t)(cc - 7) * 32768;
        }
        MBARRIER_EXPECT_TX(mbar, 40960u);
        CP_BULK(base + A_OFF, aSrc, 8192u, mbar);
        CP_BULK(base + B_OFF, bSrc, 32768u, mbar);
    };

    if (tid == 0) { issue(0); issue(1); }

    for (int graph = 0; graph < 2; graph++) {
        const int NC = graph ? 5 : 7;
        __half* stash = (__half*)(dsm + (graph ? STASH_R_OFF : STASH_E_OFF));
        const float* bias_s =
            (const float*)(dsm + (graph ? BIAS_R_OFF : BIAS_E_OFF));

        float acc[2][8][4];
        #pragma unroll
        for (int mi = 0; mi < 2; mi++)
            #pragma unroll
            for (int ni = 0; ni < 8; ni++)
                #pragma unroll
                for (int q = 0; q < 4; q++) acc[mi][ni][q] = 0.f;

        for (int c = 0; c < NC; c++) {
            const int cc = graph ? 7 + c : c;
            MBARRIER_WAIT_PARITY(sb + MBAR_OFF + (cc % 3) * 8, (cc / 3) & 1);
            __syncthreads();
            if (tid == 0 && cc + 2 < 12) issue(cc + 2);

            const uint32_t base = sb + (cc % 3) * STAGE_SZ;
            #pragma unroll
            for (int ks = 0; ks < 4; ks++) {
                uint32_t ah[2][4];
                #pragma unroll
                for (int mi = 0; mi < 2; mi++) {
                    const int ar = warp_m * 32 + mi * 16 + i8 + (sub & 1) * 8;
                    const int akg = ks * 2 + (sub >> 1);
                    const uint32_t off =
                        (uint32_t)(ar * 64 + ((akg ^ (ar & 7)) * 8)) * 2u;
                    LDSM_X4(ah[mi][0], ah[mi][1], ah[mi][2], ah[mi][3],
                            base + A_OFF + off);
                }
                #pragma unroll
                for (int p = 0; p < 4; p++) {
                    const int nn = warp_n * 64 + p * 16 + i8 + (sub >> 1) * 8;
                    const int bkg = ks * 2 + (sub & 1);
                    const uint32_t off =
                        (uint32_t)(nn * 64 + ((bkg ^ (nn & 7)) * 8)) * 2u;
                    uint32_t b0, b1, b2, b3;
                    LDSM_X4(b0, b1, b2, b3, base + B_OFF + off);
                    #pragma unroll
                    for (int mi = 0; mi < 2; mi++) {
                        MMA16816(acc[mi][2 * p],     ah[mi], b0, b1);
                        MMA16816(acc[mi][2 * p + 1], ah[mi], b2, b3);
                    }
                }
            }
        }

        const int g8 = lane >> 2, tg = lane & 3;
        #pragma unroll
        for (int mi = 0; mi < 2; mi++) {
            const int row0 = warp_m * 32 + mi * 16 + g8;
            #pragma unroll
            for (int ni = 0; ni < 8; ni++) {
                const int col = warp_n * 64 + ni * 8 + tg * 2;
                const float b0 = bias_s[col], b1 = bias_s[col + 1];
                *(__half2*)(stash + row0 * STASH_STRIDE + col) =
                    __floats2half2_rn(acc[mi][ni][0] + b0, acc[mi][ni][1] + b1);
                *(__half2*)(stash + (row0 + 8) * STASH_STRIDE + col) =
                    __floats2half2_rn(acc[mi][ni][2] + b0, acc[mi][ni][3] + b1);
            }
        }
    }
    __syncthreads();

    // ---- ehr mini-GEMM: ehrp = relu(ehr @ We + be) ----
    {
        #pragma unroll
        for (int it = 0; it < 2; it++) {
            const int idx = tid + it * 256;
            const int row = idx >> 3, g = idx & 7;
            const __half* src = g_Ah_ehr + (size_t)(bm * 64 + row) * 64 + g * 8;
            const uint32_t off = (uint32_t)(row * 8 + (g ^ (row & 7))) * 16u;
            CP_ASYNC16(sb + A_OFF + off, (const void*)src);
        }
        #pragma unroll
        for (int it = 0; it < 2; it++) {
            const int idx = tid + it * 256;
            const int row = idx >> 3, g = idx & 7;
            const __half* src = g_WeT + (size_t)row * 64 + g * 8;
            const uint32_t off = (uint32_t)(row * 8 + (g ^ (row & 7))) * 16u;
            CP_ASYNC16(sb + B_OFF + off, (const void*)src);
        }
        CP_COMMIT();
        CP_WAIT0();
        __syncthreads();

        float accH[2][2][4];
        #pragma unroll
        for (int mi = 0; mi < 2; mi++)
            #pragma unroll
            for (int ni = 0; ni < 2; ni++)
                #pragma unroll
                for (int q = 0; q < 4; q++) accH[mi][ni][q] = 0.f;

        #pragma unroll
        for (int ks = 0; ks < 4; ks++) {
            uint32_t ah[2][4];
            #pragma unroll
            for (int mi = 0; mi < 2; mi++) {
                const int ar = warp_m * 32 + mi * 16 + i8 + (sub & 1) * 8;
                const int akg = ks * 2 + (sub >> 1);
                const uint32_t off =
                    (uint32_t)(ar * 64 + ((akg ^ (ar & 7)) * 8)) * 2u;
                LDSM_X4(ah[mi][0], ah[mi][1], ah[mi][2], ah[mi][3],
                        sb + A_OFF + off);
            }
            const int nn = warp_n * 16 + i8 + (sub >> 1) * 8;
            const int bkg = ks * 2 + (sub & 1);
            const uint32_t off =
                (uint32_t)(nn * 64 + ((bkg ^ (nn & 7)) * 8)) * 2u;
            uint32_t b0, b1, b2, b3;
            LDSM_X4(b0, b1, b2, b3, sb + B_OFF + off);
            #pragma unroll
            for (int mi = 0; mi < 2; mi++) {
                MMA16816(accH[mi][0], ah[mi], b0, b1);
                MMA16816(accH[mi][1], ah[mi], b2, b3);
            }
        }

        float* ehrp = (float*)(dsm + EHRP_OFF);
        const int g8 = lane >> 2, tg = lane & 3;
        #pragma unroll
        for (int mi = 0; mi < 2; mi++) {
            const int row0 = warp_m * 32 + mi * 16 + g8;
            #pragma unroll
            for (int ni = 0; ni < 2; ni++) {
                const int col = warp_n * 16 + ni * 8 + tg * 2;
                const float b0 = __ldg(be + col), b1 = __ldg(be + col + 1);
                ehrp[row0 * 64 + col]       = fmaxf(accH[mi][ni][0] + b0, 0.f);
                ehrp[row0 * 64 + col + 1]   = fmaxf(accH[mi][ni][1] + b1, 0.f);
                ehrp[(row0 + 8) * 64 + col] = fmaxf(accH[mi][ni][2] + b0, 0.f);
                ehrp[(row0 + 8) * 64 + col + 1] =
                    fmaxf(accH[mi][ni][3] + b1, 0.f);
            }
        }
    }
    __syncthreads();

    // ---- epilogue (warp-per-row, all from smem) ----
    const __half* stash_e = (const __half*)(dsm + STASH_E_OFF);
    const __half* stash_r = (const __half*)(dsm + STASH_R_OFF);
    const float* ehrp     = (const float*)(dsm + EHRP_OFF);
    const float ba0 = ba[0], bf0 = bf2[0];
    float wa[8], wf[8];
    #pragma unroll
    for (int j = 0; j < 8; j++) {
        wa[j] = Wa[lane + 32 * j];
        wf[j] = Wf2[lane + 32 * j];
    }
    const float wfe0 = Wf2[256 + lane], wfe1 = Wf2[256 + lane + 32];

    #pragma unroll 2
    for (int q = 0; q < 8; q++) {
        const int row = wid * 8 + q;
        float e[8], r[8];
        #pragma unroll
        for (int j = 0; j < 8; j++) {
            e[j] = __half2float(stash_e[row * STASH_STRIDE + lane + 32 * j]);
            r[j] = __half2float(stash_r[row * STASH_STRIDE + lane + 32 * j]);
        }
        const float o0 = ehrp[row * 64 + lane];
        const float o1 = ehrp[row * 64 + lane + 32];

        float s = 0.f;
        #pragma unroll
        for (int j = 0; j < 8; j++)
            s = fmaf(tanh_fast(e[j] + r[j]), wa[j], s);
        #pragma unroll
        for (int off = 16; off > 0; off >>= 1)
            s += __shfl_xor_sync(0xffffffffu, s, off);
        const float attn = 1.f / (1.f + __expf(-(s + ba0)));

        float v = o0 * wfe0 + o1 * wfe1;
        #pragma unroll
        for (int j = 0; j < 8; j++) {
            const float f = attn * e[j] + (1.f - attn) * r[j];
            v = fmaf(fmaxf(f, 0.f), wf[j], v);
        }
        #pragma unroll
        for (int off = 16; off > 0; off >>= 1)
            v += __shfl_xor_sync(0xffffffffu, v, off);
        if (lane == 0)
            out[bm * 64 + row] = 1.f / (1.f + __expf(-(v + bf0)));
    }
}

// ============================================================================
extern "C" void kernel_launch(void* const* d_in, const int* in_sizes, int n_in,
                              void* d_out, int out_size) {
    const float* ecc    = (const float*)d_in[0];
    const float* err    = (const float*)d_in[1];
    const float* ehr    = (const float*)d_in[2];
    const float* wt_ecc = (const float*)d_in[3];
    const float* bt_ecc = (const float*)d_in[4];
    const float* wt_err = (const float*)d_in[5];
    const float* bt_err = (const float*)d_in[6];
    const float* W0_ecc = (const float*)d_in[7];
    const float* W1_ecc = (const float*)d_in[8];
    const float* b_ecc  = (const float*)d_in[9];
    const float* W0_err = (const float*)d_in[10];
    const float* W1_err = (const float*)d_in[11];
    const float* b_err  = (const float*)d_in[12];
    const float* Wp_ecc = (const float*)d_in[13];
    const float* bp_ecc = (const float*)d_in[14];
    const float* Wp_err = (const float*)d_in[15];
    const float* bp_err = (const float*)d_in[16];
    const float* Wa     = (const float*)d_in[17];
    const float* ba     = (const float*)d_in[18];
    const float* We     = (const float*)d_in[19];
    const float* be     = (const float*)d_in[20];
    const float* Wf2    = (const float*)d_in[21];
    const float* bf2    = (const float*)d_in[22];

    cudaFuncSetAttribute(fused_kernel,
                         cudaFuncAttributeMaxDynamicSharedMemorySize, FUSED_SMEM);

    precompute<<<745, 256>>>(ecc, err, ehr,
                             wt_ecc, bt_ecc, wt_err, bt_err,
                             W0_ecc, W1_ecc, b_ecc, W0_err, W1_err, b_err,
                             Wp_ecc, bp_ecc, Wp_err, bp_err, We);
    fused_kernel<<<128, 256, FUSED_SMEM>>>(Wa, ba, be, Wf2, bf2,
                                           (float*)d_out);
}

// round 15
// speedup vs baseline: 1.1800x; 1.1672x over previous
#include <cuda_runtime.h>
#include <cuda_fp16.h>
#include <math.h>
#include <stdint.h>

#define B_TOT 8192

// ============================================================================
// Device globals (row-major fp16, R12 layout)
// ============================================================================
__device__ __align__(16) __half g_B_ecc[256 * 448];   // R^T fp16
__device__ __align__(16) __half g_B_err[256 * 320];
__device__ __align__(16) __half g_WeT[64 * 64];       // We^T fp16 [n][k]
__device__ __align__(16) __half g_Ah_ecc[B_TOT * 448];
__device__ __align__(16) __half g_Ah_err[B_TOT * 320];
__device__ __align__(16) __half g_Ah_ehr[B_TOT * 64];
__device__ float g_bias_part[28 * 256];

// ---------------------------------------------------------------------------
#define MMA16816(d, a, b0_, b1_) \
    asm volatile( \
        "mma.sync.aligned.m16n8k16.row.col.f32.f16.f16.f32 " \
        "{%0,%1,%2,%3}, {%4,%5,%6,%7}, {%8,%9}, {%0,%1,%2,%3};" \
        : "+f"((d)[0]), "+f"((d)[1]), "+f"((d)[2]), "+f"((d)[3]) \
        : "r"((a)[0]), "r"((a)[1]), "r"((a)[2]), "r"((a)[3]), \
          "r"(b0_), "r"(b1_))

#define LDSM_X4(r0, r1, r2, r3, addr) \
    asm volatile( \
        "ldmatrix.sync.aligned.m8n8.x4.shared.b16 {%0,%1,%2,%3}, [%4];" \
        : "=r"(r0), "=r"(r1), "=r"(r2), "=r"(r3) : "r"(addr))

#define CP_ASYNC16(dst, src) \
    asm volatile("cp.async.cg.shared.global [%0], [%1], 16;" \
        :: "r"(dst), "l"(src) : "memory")
#define CP_COMMIT() asm volatile("cp.async.commit_group;" ::: "memory")
#define CP_WAIT0()  asm volatile("cp.async.wait_group 0;" ::: "memory")
#define CP_WAIT1()  asm volatile("cp.async.wait_group 1;" ::: "memory")

__device__ __forceinline__ uint32_t smem_to_u32(const void* p) {
    uint32_t a;
    asm("{ .reg .u64 t; cvta.to.shared.u64 t, %1; cvt.u32.u64 %0, t; }"
        : "=r"(a) : "l"(p));
    return a;
}
__device__ __forceinline__ uint32_t pack_hi16(float a, float b) {
    return (uint32_t)__half_as_ushort(__float2half(a)) |
           ((uint32_t)__half_as_ushort(__float2half(b)) << 16);
}
__device__ __forceinline__ float tanh_fast(float x) {
    float y;
    asm("tanh.approx.f32 %0, %1;" : "=f"(y) : "f"(x));
    return y;
}

// ============================================================================
// K1: merged precompute + fp16 conversions (R12 version, row-major outputs).
//  0..139   : R rows (Weff inline)      140..167: c0 + bias_part
//  168      : We^T fp16                 169..424: ecc -> fp16 (32 rows/blk)
//  425..680 : err -> fp16 (32 rows/blk) 681..744: ehr -> fp16 (128 rows/blk)
// ============================================================================
__global__ __launch_bounds__(256) void precompute(
    const float* __restrict__ ecc, const float* __restrict__ err,
    const float* __restrict__ ehr,
    const float* __restrict__ wt_ecc, const float* __restrict__ bt_ecc,
    const float* __restrict__ wt_err, const float* __restrict__ bt_err,
    const float* __restrict__ W0_ecc, const float* __restrict__ W1_ecc,
    const float* __restrict__ b_ecc,
    const float* __restrict__ W0_err, const float* __restrict__ W1_err,
    const float* __restrict__ b_err,
    const float* __restrict__ Wp_ecc, const float* __restrict__ bp_ecc,
    const float* __restrict__ Wp_err, const float* __restrict__ bp_err,
    const float* __restrict__ We)
{
    const int blk = blockIdx.x;
    const int t   = threadIdx.x;

    if (blk < 140) {
        // ------------------- R rows with inline Weff -------------------
        const int graph = (blk >= 80);
        const int rel   = graph ? blk - 80 : blk;
        const int u     = rel / 5;
        const int tpg   = rel % 5;
        const int V     = graph ? 12 : 16;
        const int K     = graph ? 300 : 400;
        const int KP    = graph ? 320 : 448;
        const float* wt = graph ? wt_err : wt_ecc;
        const float* W0 = graph ? W0_err : W0_ecc;
        const float* W1 = graph ? W1_err : W1_ecc;
        const float* Wp = graph ? Wp_err : Wp_ecc;
        __half* B = graph ? g_B_err : g_B_ecc;

        __shared__ float wts[96];
        __shared__ float w0s[5 * 64];
        __shared__ float w1s[5 * 64];
        if (t < 96) wts[t] = wt[t];
        __syncthreads();

        for (int idx = t; idx < 320; idx += 256) {
            const int j = idx >> 6, g = idx & 63;
            const int tp = tpg * 5 + j;
            float s0 = 0.f, s1 = 0.f;
            #pragma unroll 4
            for (int c = 0; c < 32; c++) {
                #pragma unroll
                for (int k = 0; k < 3; k++) {
                    const int tt = tp - k + 1;
                    if (tt >= 0 && tt < 25) {
                        const float w = wts[c * 3 + k];
                        s0 = fmaf(w, W0[(c * 25 + tt) * 64 + g], s0);
                        s1 = fmaf(w, W1[(c * 25 + tt) * 64 + g], s1);
                    }
                }
            }
            w0s[idx] = s0;
            w1s[idx] = -0.5f * s1;
        }
        __syncthreads();

        const int h  = t;
        const int up = (u + 1) % V;
        const int um = (u + V - 1) % V;

        float acc[5] = {0.f, 0.f, 0.f, 0.f, 0.f};
        const float* WpU = Wp + (size_t)(u  * 64) * 256 + h;
        const float* WpP = Wp + (size_t)(up * 64) * 256 + h;
        const float* WpM = Wp + (size_t)(um * 64) * 256 + h;

        #pragma unroll 4
        for (int gg = 0; gg < 64; gg++) {
            const float wp_u = WpU[gg * 256];
            const float wp_s = WpP[gg * 256] + WpM[gg * 256];
            #pragma unroll
            for (int j = 0; j < 5; j++) {
                acc[j] = fmaf(w0s[j * 64 + gg], wp_u, acc[j]);
                acc[j] = fmaf(w1s[j * 64 + gg], wp_s, acc[j]);
            }
        }

        #pragma unroll
        for (int j = 0; j < 5; j++) {
            const int k = u * 25 + tpg * 5 + j;
            B[(size_t)h * KP + k] = __float2half(acc[j]);
        }
        if (u == 0 && tpg == 0) {
            for (int k = K; k < KP; k++)
                B[(size_t)h * KP + k] = __ushort_as_half((unsigned short)0);
        }
    } else if (blk < 168) {
        // ------------------- c0 + bias_part -------------------
        const int rel   = blk - 140;
        const int graph = (rel >= 16);
        const int u     = graph ? rel - 16 : rel;
        const float* bt = graph ? bt_err : bt_ecc;
        const float* W0 = graph ? W0_err : W0_ecc;
        const float* W1 = graph ? W1_err : W1_ecc;
        const float* bb = graph ? b_err  : b_ecc;
        const float* Wp = graph ? Wp_err : Wp_ecc;
        const float* bp = graph ? bp_err : bp_ecc;

        __shared__ float part[256];
        __shared__ float c0s[64];

        const int g = t & 63, cb = (t >> 6) * 8;
        float s = 0.f;
        #pragma unroll
        for (int ci = 0; ci < 8; ci++) {
            const int c = cb + ci;
            float a = 0.f;
            #pragma unroll
            for (int tt = 0; tt < 25; tt++)
                a += W0[(c * 25 + tt) * 64 + g] - W1[(c * 25 + tt) * 64 + g];
            s = fmaf(bt[c], a, s);
        }
        part[t] = s;
        __syncthreads();
        if (t < 64)
            c0s[g] = part[g] + part[64 + g] + part[128 + g] + part[192 + g] + bb[g];
        __syncthreads();

        const int h = t;
        float pbias = (u == 0) ? bp[h] : 0.f;
        const float* WpU = Wp + (size_t)(u * 64) * 256 + h;
        #pragma unroll 8
        for (int gg = 0; gg < 64; gg++)
            pbias = fmaf(c0s[gg], WpU[gg * 256], pbias);
        g_bias_part[((graph ? 16 : 0) + u) * 256 + h] = pbias;
    } else if (blk == 168) {
        // ------------------- We^T fp16 -------------------
        for (int i = t; i < 4096; i += 256) {
            const int n = i >> 6, k = i & 63;
            g_WeT[n * 64 + k] = __float2half(We[k * 64 + n]);
        }
    } else if (blk < 425) {
        // ------------------- ecc -> fp16, KP=448 -------------------
        const int r0 = (blk - 169) * 32;
        for (int idx = t; idx < 32 * 56; idx += 256) {
            const int row = idx / 56, gg = idx - row * 56;
            uint4 v = make_uint4(0u, 0u, 0u, 0u);
            if (gg < 50) {
                const float* s = ecc + (size_t)(r0 + row) * 400 + gg * 8;
                const float4 a = *(const float4*)s;
                const float4 b = *(const float4*)(s + 4);
                v.x = pack_hi16(a.x, a.y); v.y = pack_hi16(a.z, a.w);
                v.z = pack_hi16(b.x, b.y); v.w = pack_hi16(b.z, b.w);
            }
            *(uint4*)(g_Ah_ecc + (size_t)(r0 + row) * 448 + gg * 8) = v;
        }
    } else if (blk < 681) {
        // ------------------- err -> fp16, KP=320 (300 real) -------------------
        const int r0 = (blk - 425) * 32;
        for (int idx = t; idx < 32 * 40; idx += 256) {
            const int row = idx / 40, gg = idx - row * 40;
            uint4 v = make_uint4(0u, 0u, 0u, 0u);
            if (gg < 37) {
                const float* s = err + (size_t)(r0 + row) * 300 + gg * 8;
                const float4 a = *(const float4*)s;
                const float4 b = *(const float4*)(s + 4);
                v.x = pack_hi16(a.x, a.y); v.y = pack_hi16(a.z, a.w);
                v.z = pack_hi16(b.x, b.y); v.w = pack_hi16(b.z, b.w);
            } else if (gg == 37) {
                const float* s = err + (size_t)(r0 + row) * 300 + 296;
                v.x = pack_hi16(s[0], s[1]); v.y = pack_hi16(s[2], s[3]);
            }
            *(uint4*)(g_Ah_err + (size_t)(r0 + row) * 320 + gg * 8) = v;
        }
    } else {
        // ------------------- ehr -> fp16 -------------------
        const int r0 = (blk - 681) * 128;
        for (int idx = t; idx < 128 * 8; idx += 256) {
            const int row = idx >> 3, gg = idx & 7;
            const float* s = ehr + (size_t)(r0 + row) * 64 + gg * 8;
            const float4 a = *(const float4*)s;
            const float4 b = *(const float4*)(s + 4);
            uint4 v;
            v.x = pack_hi16(a.x, a.y); v.y = pack_hi16(a.z, a.w);
            v.z = pack_hi16(b.x, b.y); v.w = pack_hi16(b.z, b.w);
            *(uint4*)(g_Ah_ehr + (size_t)(r0 + row) * 64 + gg * 8) = v;
        }
    }
}

// ============================================================================
// K2: FUSED GEMM + ehr-MMA + epilogue. 128 blocks x 64 batch rows.
// NOW 512 THREADS (16 warps, warp tiles 16x64) — the fused kernel is
// latency-bound (occ 12.7%, issue 21%), so double the warps per scheduler.
// Staging identical to R12 (per-16B cp.async, 3 stages, one sync per chunk).
// ============================================================================
#define A_OFF        0
#define B_OFF        8192
#define STAGE_SZ     40960
#define EHRP_OFF     40960
#define STASH_E_OFF  122880
#define STASH_STRIDE 264
#define STASH_R_OFF  156672
#define BIAS_E_OFF   190464
#define BIAS_R_OFF   191488
#define FUSED_SMEM   192512

__global__ __launch_bounds__(512, 1) void fused_kernel(
    const float* __restrict__ Wa, const float* __restrict__ ba,
    const float* __restrict__ be,
    const float* __restrict__ Wf2, const float* __restrict__ bf2,
    float* __restrict__ out)
{
    extern __shared__ char dsm[];
    const uint32_t sb = smem_to_u32(dsm);
    const int tid = threadIdx.x, lane = tid & 31, wid = tid >> 5;
    const int bm = blockIdx.x;

    // ---- bias sums ----
    if (tid < 256) {
        float s = 0.f;
        #pragma unroll
        for (int u = 0; u < 16; u++) s += g_bias_part[u * 256 + tid];
        ((float*)(dsm + BIAS_E_OFF))[tid] = s;
        s = 0.f;
        #pragma unroll
        for (int u = 0; u < 12; u++) s += g_bias_part[(16 + u) * 256 + tid];
        ((float*)(dsm + BIAS_R_OFF))[tid] = s;
    }
    __syncthreads();

    const int warp_m = wid & 3;      // 0..3 -> 16 rows each
    const int warp_n = wid >> 2;     // 0..3 -> 64 cols each
    const int sub = lane >> 3, i8 = lane & 7;

    for (int graph = 0; graph < 2; graph++) {
        const int KP = graph ? 320 : 448;
        const int NC = graph ? 5 : 7;
        const __half* Ap = graph ? g_Ah_err : g_Ah_ecc;
        const __half* Bp = graph ? g_B_err : g_B_ecc;
        __half* stash = (__half*)(dsm + (graph ? STASH_R_OFF : STASH_E_OFF));
        const float* bias_s =
            (const float*)(dsm + (graph ? BIAS_R_OFF : BIAS_E_OFF));

        float acc[8][4];
        #pragma unroll
        for (int ni = 0; ni < 8; ni++)
            #pragma unroll
            for (int q = 0; q < 4; q++) acc[ni][q] = 0.f;

        auto issueAB = [&](int c) {
            const uint32_t base = sb + (c % 3) * STAGE_SZ;
            {   // A: 512 granules, one per thread
                const int row = tid >> 3, g = tid & 7;
                const __half* src =
                    Ap + (size_t)(bm * 64 + row) * KP + c * 64 + g * 8;
                const uint32_t off = (uint32_t)(row * 8 + (g ^ (row & 7))) * 16u;
                CP_ASYNC16(base + A_OFF + off, (const void*)src);
            }
            #pragma unroll
            for (int it = 0; it < 4; it++) {   // B: 2048 granules
                const int idx = tid + it * 512;
                const int row = idx >> 3, g = idx & 7;
                const __half* src = Bp + (size_t)row * KP + c * 64 + g * 8;
                const uint32_t off = (uint32_t)(row * 8 + (g ^ (row & 7))) * 16u;
                CP_ASYNC16(base + B_OFF + off, (const void*)src);
            }
            CP_COMMIT();
        };
        auto compute = [&](int c) {
            const uint32_t base = sb + (c % 3) * STAGE_SZ;
            #pragma unroll
            for (int ks = 0; ks < 4; ks++) {
                uint32_t ah[4];
                {
                    const int ar = warp_m * 16 + i8 + (sub & 1) * 8;
                    const int akg = ks * 2 + (sub >> 1);
                    const uint32_t off =
                        (uint32_t)(ar * 64 + ((akg ^ (ar & 7)) * 8)) * 2u;
                    LDSM_X4(ah[0], ah[1], ah[2], ah[3], base + A_OFF + off);
                }
                #pragma unroll
                for (int p = 0; p < 4; p++) {
                    const int nn = warp_n * 64 + p * 16 + i8 + (sub >> 1) * 8;
                    const int bkg = ks * 2 + (sub & 1);
                    const uint32_t off =
                        (uint32_t)(nn * 64 + ((bkg ^ (nn & 7)) * 8)) * 2u;
                    uint32_t b0, b1, b2, b3;
                    LDSM_X4(b0, b1, b2, b3, base + B_OFF + off);
                    MMA16816(acc[2 * p],     ah, b0, b1);
                    MMA16816(acc[2 * p + 1], ah, b2, b3);
                }
            }
        };

        // ---- 3-stage pipeline, one sync per chunk ----
        issueAB(0);
        issueAB(1);
        for (int c = 0; c < NC; c++) {
            if (c + 1 < NC) { CP_WAIT1(); } else { CP_WAIT0(); }
            __syncthreads();
            if (c + 2 < NC) issueAB(c + 2);
            compute(c);
        }
        __syncthreads();

        // ---- writeback to fp16 stash (+bias) ----
        const int g8 = lane >> 2, tg = lane & 3;
        {
            const int row0 = warp_m * 16 + g8;
            #pragma unroll
            for (int ni = 0; ni < 8; ni++) {
                const int col = warp_n * 64 + ni * 8 + tg * 2;
                const float b0 = bias_s[col], b1 = bias_s[col + 1];
                *(__half2*)(stash + row0 * STASH_STRIDE + col) =
                    __floats2half2_rn(acc[ni][0] + b0, acc[ni][1] + b1);
                *(__half2*)(stash + (row0 + 8) * STASH_STRIDE + col) =
                    __floats2half2_rn(acc[ni][2] + b0, acc[ni][3] + b1);
            }
        }
    }

    // ---- ehr mini-GEMM: ehrp = relu(ehr @ We + be) ----
    {
        {   // A: 512 granules
            const int row = tid >> 3, g = tid & 7;
            const __half* src = g_Ah_ehr + (size_t)(bm * 64 + row) * 64 + g * 8;
            const uint32_t off = (uint32_t)(row * 8 + (g ^ (row & 7))) * 16u;
            CP_ASYNC16(sb + A_OFF + off, (const void*)src);
        }
        {   // B (WeT): 512 granules
            const int row = tid >> 3, g = tid & 7;
            const __half* src = g_WeT + (size_t)row * 64 + g * 8;
            const uint32_t off = (uint32_t)(row * 8 + (g ^ (row & 7))) * 16u;
            CP_ASYNC16(sb + B_OFF + off, (const void*)src);
        }
        CP_COMMIT();
        CP_WAIT0();
        __syncthreads();

        float accH[2][4];
        #pragma unroll
        for (int ni = 0; ni < 2; ni++)
            #pragma unroll
            for (int q = 0; q < 4; q++) accH[ni][q] = 0.f;

        #pragma unroll
        for (int ks = 0; ks < 4; ks++) {
            uint32_t ah[4];
            {
                const int ar = warp_m * 16 + i8 + (sub & 1) * 8;
                const int akg = ks * 2 + (sub >> 1);
                const uint32_t off =
                    (uint32_t)(ar * 64 + ((akg ^ (ar & 7)) * 8)) * 2u;
                LDSM_X4(ah[0], ah[1], ah[2], ah[3], sb + A_OFF + off);
            }
            const int nn = warp_n * 16 + i8 + (sub >> 1) * 8;
            const int bkg = ks * 2 + (sub & 1);
            const uint32_t off =
                (uint32_t)(nn * 64 + ((bkg ^ (nn & 7)) * 8)) * 2u;
            uint32_t b0, b1, b2, b3;
            LDSM_X4(b0, b1, b2, b3, sb + B_OFF + off);
            MMA16816(accH[0], ah, b0, b1);
            MMA16816(accH[1], ah, b2, b3);
        }

        float* ehrp = (float*)(dsm + EHRP_OFF);
        const int g8 = lane >> 2, tg = lane & 3;
        {
            const int row0 = warp_m * 16 + g8;
            #pragma unroll
            for (int ni = 0; ni < 2; ni++) {
                const int col = warp_n * 16 + ni * 8 + tg * 2;
                const float b0 = __ldg(be + col), b1 = __ldg(be + col + 1);
                ehrp[row0 * 64 + col]       = fmaxf(accH[ni][0] + b0, 0.f);
                ehrp[row0 * 64 + col + 1]   = fmaxf(accH[ni][1] + b1, 0.f);
                ehrp[(row0 + 8) * 64 + col] = fmaxf(accH[ni][2] + b0, 0.f);
                ehrp[(row0 + 8) * 64 + col + 1] =
                    fmaxf(accH[ni][3] + b1, 0.f);
            }
        }
    }
    __syncthreads();

    // ---- epilogue (warp-per-row: 16 warps x 4 rows) ----
    const __half* stash_e = (const __half*)(dsm + STASH_E_OFF);
    const __half* stash_r = (const __half*)(dsm + STASH_R_OFF);
    const float* ehrp     = (const float*)(dsm + EHRP_OFF);
    const float ba0 = ba[0], bf0 = bf2[0];
    float wa[8], wf[8];
    #pragma unroll
    for (int j = 0; j < 8; j++) {
        wa[j] = Wa[lane + 32 * j];
        wf[j] = Wf2[lane + 32 * j];
    }
    const float wfe0 = Wf2[256 + lane], wfe1 = Wf2[256 + lane + 32];

    #pragma unroll
    for (int q = 0; q < 4; q++) {
        const int row = wid * 4 + q;
        float e[8], r[8];
        #pragma unroll
        for (int j = 0; j < 8; j++) {
            e[j] = __half2float(stash_e[row * STASH_STRIDE + lane + 32 * j]);
            r[j] = __half2float(stash_r[row * STASH_STRIDE + lane + 32 * j]);
        }
        const float o0 = ehrp[row * 64 + lane];
        const float o1 = ehrp[row * 64 + lane + 32];

        float s = 0.f;
        #pragma unroll
        for (int j = 0; j < 8; j++)
            s = fmaf(tanh_fast(e[j] + r[j]), wa[j], s);
        #pragma unroll
        for (int off = 16; off > 0; off >>= 1)
            s += __shfl_xor_sync(0xffffffffu, s, off);
        const float attn = 1.f / (1.f + __expf(-(s + ba0)));

        float v = o0 * wfe0 + o1 * wfe1;
        #pragma unroll
        for (int j = 0; j < 8; j++) {
            const float f = attn * e[j] + (1.f - attn) * r[j];
            v = fmaf(fmaxf(f, 0.f), wf[j], v);
        }
        #pragma unroll
        for (int off = 16; off > 0; off >>= 1)
            v += __shfl_xor_sync(0xffffffffu, v, off);
        if (lane == 0)
            out[bm * 64 + row] = 1.f / (1.f + __expf(-(v + bf0)));
    }
}

// ============================================================================
extern "C" void kernel_launch(void* const* d_in, const int* in_sizes, int n_in,
                              void* d_out, int out_size) {
    const float* ecc    = (const float*)d_in[0];
    const float* err    = (const float*)d_in[1];
    const float* ehr    = (const float*)d_in[2];
    const float* wt_ecc = (const float*)d_in[3];
    const float* bt_ecc = (const float*)d_in[4];
    const float* wt_err = (const float*)d_in[5];
    const float* bt_err = (const float*)d_in[6];
    const float* W0_ecc = (const float*)d_in[7];
    const float* W1_ecc = (const float*)d_in[8];
    const float* b_ecc  = (const float*)d_in[9];
    const float* W0_err = (const float*)d_in[10];
    const float* W1_err = (const float*)d_in[11];
    const float* b_err  = (const float*)d_in[12];
    const float* Wp_ecc = (const float*)d_in[13];
    const float* bp_ecc = (const float*)d_in[14];
    const float* Wp_err = (const float*)d_in[15];
    const float* bp_err = (const float*)d_in[16];
    const float* Wa     = (const float*)d_in[17];
    const float* ba     = (const float*)d_in[18];
    const float* We     = (const float*)d_in[19];
    const float* be     = (const float*)d_in[20];
    const float* Wf2    = (const float*)d_in[21];
    const float* bf2    = (const float*)d_in[22];

    cudaFuncSetAttribute(fused_kernel,
                         cudaFuncAttributeMaxDynamicSharedMemorySize, FUSED_SMEM);

    precompute<<<745, 256>>>(ecc, err, ehr,
                             wt_ecc, bt_ecc, wt_err, bt_err,
                             W0_ecc, W1_ecc, b_ecc, W0_err, W1_err, b_err,
                             Wp_ecc, bp_ecc, Wp_err, bp_err, We);
    fused_kernel<<<128, 512, FUSED_SMEM>>>(Wa, ba, be, Wf2, bf2,
                                           (float*)d_out);
}